// round 17
// baseline (speedup 1.0000x reference)
#include <cuda_runtime.h>
#include <cstdint>

// Problem constants (fixed by setup_inputs)
#define M_PTS   1024
#define BATCH   2
#define NC      64
#define NCEN    (BATCH * NC)       // 128 centers
#define KS      13
#define NA      20
#define DOUT    64
#define KP      (KS * NA)          // 260 kernel positions
#define R2      0.16f              // RADIUS^2
// S = -log2(e) / (2*SIGMA) = -1.4426950408889634 / 0.16
#define S_CONST (-9.016844005556021f)
#define M2S     (18.033688011112042f)   // -2*S

#define CLU      2                 // CTAs per center (cluster size)
#define HALF_PTS (M_PTS / CLU)     // 512 points per CTA
#define NT       544               // 17 warps
#define NW       (NT / 32)
// kps with index < KP3 have 3 workers; the rest have 2 (NT = 3*KP3 + 2*(KP-KP3))
#define KP3      (NT - 2 * KP)     // 24
#define OUT_PER  (DOUT * NA / CLU) // 640 conv outputs per CTA

__device__ __forceinline__ float ex2(float x) {
    float y;
    asm("ex2.approx.ftz.f32 %0, %1;" : "=f"(y) : "f"(x));
    return y;
}
__device__ __forceinline__ uint32_t smem_u32(const void* p) {
    uint32_t a;
    asm("{ .reg .u64 t; cvta.to.shared.u64 t, %1; cvt.u32.u64 %0, t; }"
        : "=r"(a) : "l"(p));
    return a;
}
__device__ __forceinline__ float dsm_f32(uint32_t laddr, uint32_t rank) {
    uint32_t r; float v;
    asm("mapa.shared::cluster.u32 %0, %1, %2;" : "=r"(r) : "r"(laddr), "r"(rank));
    asm volatile("ld.shared::cluster.f32 %0, [%1];" : "=f"(v) : "r"(r));
    return v;
}
__device__ __forceinline__ int dsm_s32(uint32_t laddr, uint32_t rank) {
    uint32_t r; int v;
    asm("mapa.shared::cluster.u32 %0, %1, %2;" : "=r"(r) : "r"(laddr), "r"(rank));
    asm volatile("ld.shared::cluster.b32 %0, [%1];" : "=r"(v) : "r"(r));
    return v;
}
#define CLUSTER_SYNC() do { \
    asm volatile("barrier.cluster.arrive.aligned;" ::: "memory"); \
    asm volatile("barrier.cluster.wait.aligned;"   ::: "memory"); \
} while (0)

__global__ __launch_bounds__(NT, 2) __cluster_dims__(CLU, 1, 1)
void kp_fused_kernel(const float* __restrict__ frag,      // (M,3)
                     const float* __restrict__ clouds,    // (B,3,NC)
                     const float* __restrict__ kernels,   // (KS,NA,3) -> [KP][3]
                     const float* __restrict__ W,         // (DOUT,KS)
                     float* __restrict__ out)             // (B,DOUT,NC,NA)
{
    __shared__ float4 s_pts[HALF_PTS];   // this CTA's compacted half
    __shared__ float  s_part[3][KP];     // per-(par,kp) partial sums
    __shared__ float  s_half[KP];        // this CTA's combined partial
    __shared__ float  s_wts[KP];
    __shared__ float  s_W[DOUT * KS];
    __shared__ int    s_wcnt[NW];
    __shared__ int    s_total;           // this CTA's in-ball count
    __shared__ int    s_cnt;             // same, exported to peer

    const int tid  = threadIdx.x;
    const int lane = tid & 31;
    const int wrp  = tid >> 5;

    const int blk    = blockIdx.x;
    const int center = blk >> 1;         // cluster index == center
    const int half   = blk & 1;          // cluster rank (cluster dims along x)
    const int bb     = center >> 6;      // / NC
    const int n      = center & 63;      // % NC

    // thread -> (kernel position, worker index). kps 0..KP3-1 get 3 workers,
    // kps KP3..259 get 2. Stride MUST equal the kp's worker count.
    const int kp   = tid % KP;
    const int par  = tid / KP;           // 0..2 (par==2 only for kp < KP3)
    const int npar = (kp < KP3) ? 3 : 2;

    const float kx = kernels[3 * kp + 0];
    const float ky = kernels[3 * kp + 1];
    const float kz = kernels[3 * kp + 2];

    const float cx = clouds[bb * 3 * NC + 0 * NC + n];
    const float cy = clouds[bb * 3 * NC + 1 * NC + n];
    const float cz = clouds[bb * 3 * NC + 2 * NC + n];

    // Preload conv weights into shared (overlaps with phase 1)
    for (int idx = tid; idx < DOUT * KS; idx += NT) s_W[idx] = W[idx];

    // ------ Phase 1: compact THIS CTA's 512-point half (one ballot round) ------
    {
        bool pred = false;
        float rx = 0.f, ry = 0.f, rz = 0.f, rn2 = 0.f;
        if (tid < HALF_PTS) {
            const int i = half * HALF_PTS + tid;
            rx = frag[3 * i + 0] - cx;
            ry = frag[3 * i + 1] - cy;
            rz = frag[3 * i + 2] - cz;
            rn2 = fmaf(rz, rz, fmaf(ry, ry, rx * rx));
            pred = rn2 < R2;
        }
        const unsigned bal = __ballot_sync(0xffffffffu, pred);
        if (lane == 0) s_wcnt[wrp] = __popc(bal);
        __syncthreads();
        int prefix = 0, total = 0;
        #pragma unroll
        for (int w = 0; w < NW; w++) {
            const int c = s_wcnt[w];
            if (w < wrp) prefix += c;
            total += c;
        }
        if (pred) {
            const int pos = prefix + __popc(bal & ((1u << lane) - 1u));
            s_pts[pos] = make_float4(rx, ry, rz, ex2(rn2 * S_CONST));
        }
        s_total = total;                 // all threads write the identical value
        __syncthreads();
    }
    const int cnt = s_total;

    // ------- Phase 2: gaussian accumulation, npar workers per kernel position --
    {
        const float ps = fmaf(kz, kz, fmaf(ky, ky, kx * kx)) * S_CONST;

        float a0 = 0.f, a1 = 0.f, a2 = 0.f, a3 = 0.f;
        const int st1 = npar, st2 = 2 * npar, st3 = 3 * npar, st4 = 4 * npar;
        int j = par;
        for (; j + st3 < cnt; j += st4) {
            const float4 r0 = s_pts[j];
            const float4 r1 = s_pts[j + st1];
            const float4 r2 = s_pts[j + st2];
            const float4 r3 = s_pts[j + st3];
            const float d0 = fmaf(r0.z, kz, fmaf(r0.y, ky, r0.x * kx));
            const float d1 = fmaf(r1.z, kz, fmaf(r1.y, ky, r1.x * kx));
            const float d2 = fmaf(r2.z, kz, fmaf(r2.y, ky, r2.x * kx));
            const float d3 = fmaf(r3.z, kz, fmaf(r3.y, ky, r3.x * kx));
            a0 = fmaf(r0.w, ex2(fmaf(d0, M2S, ps)), a0);
            a1 = fmaf(r1.w, ex2(fmaf(d1, M2S, ps)), a1);
            a2 = fmaf(r2.w, ex2(fmaf(d2, M2S, ps)), a2);
            a3 = fmaf(r3.w, ex2(fmaf(d3, M2S, ps)), a3);
        }
        for (; j < cnt; j += st1) {
            const float4 r0 = s_pts[j];
            const float d0 = fmaf(r0.z, kz, fmaf(r0.y, ky, r0.x * kx));
            a0 = fmaf(r0.w, ex2(fmaf(d0, M2S, ps)), a0);
        }
        s_part[par][kp] = (a0 + a1) + (a2 + a3);
        // ghost slots: kp KP3..259 have no par-2 worker (single writer each)
        for (int idx = tid; idx < KP - KP3; idx += NT) s_part[2][KP3 + idx] = 0.f;
    }
    __syncthreads();

    // ---- local combine (fixed order) + export count, then cluster barrier -----
    if (tid < KP)
        s_half[tid] = (s_part[0][tid] + s_part[1][tid]) + s_part[2][tid];
    if (tid == 0) s_cnt = cnt;
    CLUSTER_SYNC();                      // makes s_half/s_cnt visible cluster-wide

    // ---- cross-CTA combine via DSMEM (fixed rank order -> deterministic) ------
    if (tid < KP) {
        const uint32_t ah = smem_u32(&s_half[tid]);
        const uint32_t ac = smem_u32(&s_cnt);
        const float v0 = dsm_f32(ah, 0);
        const float v1 = dsm_f32(ah, 1);
        const int   c0 = dsm_s32(ac, 0);
        const int   c1 = dsm_s32(ac, 1);
        s_wts[tid] = __fdividef(v0 + v1, (float)(c0 + c1) + 1.0f);
    }
    __syncthreads();

    // ---------------- Phase 3: 1x1 SO3 conv + store (this CTA's half) ----------
    // feats[b,o,n,a] = sum_k W[o,k] * wts[k*NA + a]; rank 0 -> o 0..31, rank 1 -> o 32..63
    for (int oa = tid; oa < OUT_PER; oa += NT) {
        const int gl = half * OUT_PER + oa;
        const int o  = gl / NA;
        const int a  = gl % NA;
        float s = 0.f;
        #pragma unroll
        for (int k = 0; k < KS; k++)
            s = fmaf(s_W[o * KS + k], s_wts[k * NA + a], s);
        out[(bb * DOUT + o) * (NC * NA) + n * NA + a] = s;
    }

    // peer may still be reading our s_half; hold SMEM alive until both finish
    CLUSTER_SYNC();
}

extern "C" void kernel_launch(void* const* d_in, const int* in_sizes, int n_in,
                              void* d_out, int out_size) {
    const float* frag    = (const float*)d_in[0];   // (1024,3)
    const float* clouds  = (const float*)d_in[1];   // (2,3,64)
    const float* kernels = (const float*)d_in[2];   // (13,20,3)
    const float* W       = (const float*)d_in[3];   // (64,13)
    float* out = (float*)d_out;                     // (2,64,64,20)

    kp_fused_kernel<<<NCEN * CLU, NT>>>(frag, clouds, kernels, W, out);
}